// round 1
// baseline (speedup 1.0000x reference)
#include <cuda_runtime.h>
#include <math.h>

#define NPTS 4096
#define BATCH 4
#define NCH 64

// 16 cost matrices (4 batches x {xy, yx, xx, yy}), fp32, row-major for their softmin.
// 16 * 4096*4096 * 4B = 1 GiB static device scratch (allowed; no cudaMalloc).
__device__ float g_C[16][NPTS * NPTS];

// Ping-pong potential buffers: [buf][batch][{f_ba, g_ab, f_aa, g_bb}][N]
__device__ float g_pot[2][BATCH][4][NPTS];

// ---------------------------------------------------------------------------
// Cost kernel: C[i,j] = 0.5 * sum_c (P[c,i] - Q[c,j])^2
// Input layout: x[b][c][n] with n contiguous (stride 4096 per channel).
// Grid: (128, 128, 16) tiles of 32x32; z = b*4 + type.
// type 0: (P=x, Q=y) -> C_xy ; 1: (y, x) -> C_yx ; 2: (x,x) ; 3: (y,y)
// ---------------------------------------------------------------------------
__global__ __launch_bounds__(256) void cost_kernel(const float* __restrict__ x,
                                                   const float* __restrict__ y) {
    int j0 = blockIdx.x * 32;
    int i0 = blockIdx.y * 32;
    int z = blockIdx.z;
    int b = z >> 2, type = z & 3;
    const float* P = (type == 1 || type == 3) ? y : x;  // rows
    const float* Q = (type == 0 || type == 3) ? y : x;  // cols

    __shared__ float Ps[NCH][32];
    __shared__ float Qs[NCH][32];

    int tid = threadIdx.x;
    const float* Pb = P + (size_t)b * NCH * NPTS;
    const float* Qb = Q + (size_t)b * NCH * NPTS;
    #pragma unroll
    for (int k = tid; k < NCH * 32; k += 256) {
        int c = k >> 5, p = k & 31;
        Ps[c][p] = Pb[c * NPTS + i0 + p];
        Qs[c][p] = Qb[c * NPTS + j0 + p];
    }
    __syncthreads();

    int tx = tid & 31;   // col within tile
    int ty = tid >> 5;   // row group 0..7 (each thread does 4 rows)
    float acc0 = 0.f, acc1 = 0.f, acc2 = 0.f, acc3 = 0.f;
    #pragma unroll
    for (int c = 0; c < NCH; c++) {
        float q = Qs[c][tx];
        float d0 = Ps[c][ty +  0] - q;
        float d1 = Ps[c][ty +  8] - q;
        float d2 = Ps[c][ty + 16] - q;
        float d3 = Ps[c][ty + 24] - q;
        acc0 = fmaf(d0, d0, acc0);
        acc1 = fmaf(d1, d1, acc1);
        acc2 = fmaf(d2, d2, acc2);
        acc3 = fmaf(d3, d3, acc3);
    }
    float* Cout = g_C[z];
    Cout[(size_t)(i0 + ty +  0) * NPTS + j0 + tx] = 0.5f * acc0;
    Cout[(size_t)(i0 + ty +  8) * NPTS + j0 + tx] = 0.5f * acc1;
    Cout[(size_t)(i0 + ty + 16) * NPTS + j0 + tx] = 0.5f * acc2;
    Cout[(size_t)(i0 + ty + 24) * NPTS + j0 + tx] = 0.5f * acc3;
}

// ---------------------------------------------------------------------------
// Softmin kernel: one block per output row. Two-pass row LSE with the shifted
// logits staged in smem so the 16 KB C row hits DRAM exactly once.
//   mode 0: init   h = logw            ; out = res
//   mode 1: scan   h = logw + pot/eps  ; out = 0.5*(self + res)
//   mode 2: final  h = logw + pot/eps  ; out = res
// Reads g_pot[srcbuf], writes g_pot[srcbuf^1].
// type 0 (ft): C_xy, h from g_ab(1) | 1 (gt): C_yx, h from f_ba(0)
// type 2 (fa): C_xx, h from f_aa(2) | 3 (gb): C_yy, h from g_bb(3)
// ---------------------------------------------------------------------------
__global__ __launch_bounds__(256) void softmin_kernel(int mode, float eps,
                                                      float inv_eps, int srcbuf) {
    int row = blockIdx.x;
    int type = blockIdx.y;
    int b = blockIdx.z;

    const float* Crow = g_C[b * 4 + type] + (size_t)row * NPTS;
    int hsrc = (type < 2) ? (type ^ 1) : type;
    const float* pot = g_pot[srcbuf][b][hsrc];

    __shared__ float4 sv[NPTS / 4];   // 16 KB
    __shared__ float sred[8];

    const float logw = -8.317766166719343f;  // -ln(4096)
    int tid = threadIdx.x;
    const float4* C4 = (const float4*)Crow;
    const float4* P4 = (const float4*)pot;

    float m = -3.0e38f;
    #pragma unroll 4
    for (int j = tid; j < NPTS / 4; j += 256) {
        float4 c = C4[j];
        float4 v;
        if (mode == 0) {
            v.x = fmaf(-c.x, inv_eps, logw);
            v.y = fmaf(-c.y, inv_eps, logw);
            v.z = fmaf(-c.z, inv_eps, logw);
            v.w = fmaf(-c.w, inv_eps, logw);
        } else {
            float4 p = P4[j];
            v.x = fmaf(-c.x, inv_eps, fmaf(p.x, inv_eps, logw));
            v.y = fmaf(-c.y, inv_eps, fmaf(p.y, inv_eps, logw));
            v.z = fmaf(-c.z, inv_eps, fmaf(p.z, inv_eps, logw));
            v.w = fmaf(-c.w, inv_eps, fmaf(p.w, inv_eps, logw));
        }
        sv[j] = v;
        m = fmaxf(m, fmaxf(fmaxf(v.x, v.y), fmaxf(v.z, v.w)));
    }
    // block max
    #pragma unroll
    for (int o = 16; o; o >>= 1) m = fmaxf(m, __shfl_xor_sync(0xffffffffu, m, o));
    if ((tid & 31) == 0) sred[tid >> 5] = m;
    __syncthreads();
    m = sred[0];
    #pragma unroll
    for (int w = 1; w < 8; w++) m = fmaxf(m, sred[w]);
    __syncthreads();  // everyone done reading sred before it is reused

    float s = 0.f;
    #pragma unroll 4
    for (int j = tid; j < NPTS / 4; j += 256) {
        float4 v = sv[j];
        s += __expf(v.x - m) + __expf(v.y - m) + __expf(v.z - m) + __expf(v.w - m);
    }
    #pragma unroll
    for (int o = 16; o; o >>= 1) s += __shfl_xor_sync(0xffffffffu, s, o);
    if ((tid & 31) == 0) sred[tid >> 5] = s;
    __syncthreads();

    if (tid == 0) {
        float tot = sred[0];
        #pragma unroll
        for (int w = 1; w < 8; w++) tot += sred[w];
        float res = -eps * (m + __logf(tot));
        if (mode == 1) res = 0.5f * (g_pot[srcbuf][b][type][row] + res);
        g_pot[srcbuf ^ 1][b][type][row] = res;
    }
}

// ---------------------------------------------------------------------------
// Final reduction: loss = (1/(B*N)) * sum_{b,i} (f_ba - f_aa + g_ab - g_bb)
// ---------------------------------------------------------------------------
__global__ __launch_bounds__(256) void reduce_kernel(float* __restrict__ out, int buf) {
    __shared__ float sred[8];
    int tid = threadIdx.x;
    float s = 0.f;
    for (int k = tid; k < BATCH * NPTS; k += 256) {
        int b = k >> 12, i = k & (NPTS - 1);
        const float* pb = &g_pot[buf][b][0][0];
        s += (pb[0 * NPTS + i] - pb[2 * NPTS + i]) +
             (pb[1 * NPTS + i] - pb[3 * NPTS + i]);
    }
    #pragma unroll
    for (int o = 16; o; o >>= 1) s += __shfl_xor_sync(0xffffffffu, s, o);
    if ((tid & 31) == 0) sred[tid >> 5] = s;
    __syncthreads();
    if (tid == 0) {
        float tot = sred[0];
        #pragma unroll
        for (int w = 1; w < 8; w++) tot += sred[w];
        out[0] = tot * (1.0f / (float)(BATCH * NPTS));
    }
}

extern "C" void kernel_launch(void* const* d_in, const int* in_sizes, int n_in,
                              void* d_out, int out_size) {
    const float* x = (const float*)d_in[0];
    const float* y = (const float*)d_in[1];
    float* out = (float*)d_out;

    // epsilon schedule: exp(arange(2*ln 16, 2*ln 0.05, 2*ln 0.9)) ++ [0.05^2]
    // 55 arange entries + 1 => 56 scan steps.
    float eps_list[56];
    {
        double start = 2.0 * log(16.0);
        double step = 2.0 * log(0.9);
        for (int k = 0; k < 55; k++)
            eps_list[k] = (float)exp(start + (double)k * step);
        eps_list[55] = (float)(0.05 * 0.05);
    }

    // Build all 16 cost matrices.
    dim3 cg(NPTS / 32, NPTS / 32, 16);
    cost_kernel<<<cg, 256>>>(x, y);

    dim3 sg(NPTS, 4, BATCH);
    int buf = 0;

    // init (eps0, h = logw only)
    softmin_kernel<<<sg, 256>>>(0, eps_list[0], 1.0f / eps_list[0], buf);
    buf ^= 1;

    // 56 scan steps with 0.5 blending
    for (int k = 0; k < 56; k++) {
        softmin_kernel<<<sg, 256>>>(1, eps_list[k], 1.0f / eps_list[k], buf);
        buf ^= 1;
    }

    // final extrapolation at blur^p, no blending
    softmin_kernel<<<sg, 256>>>(2, eps_list[55], 1.0f / eps_list[55], buf);
    buf ^= 1;

    reduce_kernel<<<1, 256>>>(out, buf);
}

// round 3
// speedup vs baseline: 1.1739x; 1.1739x over previous
#include <cuda_runtime.h>
#include <math.h>

#define NPTS 4096
#define BATCH 4
#define NMAT 12               // 4 batches x {xy, xx, yy}
#define FLTMAX 3.402823466e38f

// 12 cost matrices, fp32: 768 MB static scratch.
__device__ float g_C[NMAT][(size_t)NPTS * NPTS];
// Ping-pong potentials: [buf][batch][{f_ba,g_ab,f_aa,g_bb}][N]
__device__ float g_pot[2][BATCH][4][NPTS];
// 0.5*|p|^2 per point: idx = b*2 + (0=x,1=y)
__device__ float g_hn[2 * BATCH][NPTS];
// LSE partials in log2 domain: row partials (complete rows for xy; partial for sym)
__device__ float g_rpm[NMAT][NPTS];
__device__ float g_rps[NMAT][NPTS];
// column partials per 64-row stripe
__device__ float g_cpm[NMAT][64][NPTS];
__device__ float g_cps[NMAT][64][NPTS];

__device__ __forceinline__ float ex2f(float x) {
    float r; asm("ex2.approx.ftz.f32 %0, %1;" : "=f"(r) : "f"(x)); return r;
}
__device__ __forceinline__ float lg2f(float x) {
    float r; asm("lg2.approx.f32 %0, %1;" : "=f"(r) : "f"(x)); return r;
}

// ---------------------------------------------------------------------------
// Half-norms: g_hn[arr][i] = 0.5 * sum_c p[c][i]^2
// ---------------------------------------------------------------------------
__global__ __launch_bounds__(256) void norm_kernel(const float* __restrict__ x,
                                                   const float* __restrict__ y) {
    int id = blockIdx.x * 256 + threadIdx.x;  // 8*4096 threads
    int arr = id >> 12, i = id & (NPTS - 1);
    const float* p = ((arr & 1) ? y : x) + (size_t)(arr >> 1) * 64 * NPTS + i;
    float s = 0.f;
    #pragma unroll 8
    for (int c = 0; c < 64; c++) { float v = p[(size_t)c * NPTS]; s = fmaf(v, v, s); }
    g_hn[arr][i] = 0.5f * s;
}

// ---------------------------------------------------------------------------
// Cost build: C[i,j] = hn_row[i] + hn_col[j] - dot(p_i, q_j).
// 64x64 tiles, 256 threads, 4x4 register tiles. Sym matrices (m>0): only
// tiles with tj <= ti are built (fused kernel reads only the lower triangle).
// ---------------------------------------------------------------------------
__global__ __launch_bounds__(256) void cost_kernel(const float* __restrict__ x,
                                                   const float* __restrict__ y) {
    int tj = blockIdx.x, ti = blockIdx.y;
    int z = blockIdx.z;
    int b = z / 3, m = z - b * 3;           // 0 xy, 1 xx, 2 yy
    if (m && tj > ti) return;
    const float* P = ((m == 2) ? y : x) + (size_t)b * 64 * NPTS;
    const float* Q = ((m == 1) ? x : y) + (size_t)b * 64 * NPTS;
    int rowArr = b * 2 + ((m == 2) ? 1 : 0);
    int colArr = b * 2 + ((m == 1) ? 0 : 1);

    __shared__ float Xs[8][64];
    __shared__ float Ys[8][64];
    int tid = threadIdx.x;
    int ty = tid >> 4, tx = tid & 15;
    int i0 = ti * 64, j0 = tj * 64;
    float acc[4][4] = {};

    for (int k = 0; k < 64; k += 8) {
        __syncthreads();
        {
            int c = tid >> 6;        // 0..3
            int ii = tid & 63;
            Xs[c][ii]     = P[(size_t)(k + c) * NPTS + i0 + ii];
            Xs[c + 4][ii] = P[(size_t)(k + c + 4) * NPTS + i0 + ii];
            Ys[c][ii]     = Q[(size_t)(k + c) * NPTS + j0 + ii];
            Ys[c + 4][ii] = Q[(size_t)(k + c + 4) * NPTS + j0 + ii];
        }
        __syncthreads();
        #pragma unroll
        for (int cc = 0; cc < 8; cc++) {
            float xr[4], yr[4];
            #pragma unroll
            for (int u = 0; u < 4; u++) { xr[u] = Xs[cc][ty * 4 + u]; yr[u] = Ys[cc][tx * 4 + u]; }
            #pragma unroll
            for (int ii = 0; ii < 4; ii++)
                #pragma unroll
                for (int jj = 0; jj < 4; jj++)
                    acc[ii][jj] = fmaf(xr[ii], yr[jj], acc[ii][jj]);
        }
    }
    float hc[4];
    #pragma unroll
    for (int jj = 0; jj < 4; jj++) hc[jj] = g_hn[colArr][j0 + tx * 4 + jj];
    float* Cm = g_C[b * 3 + m];
    #pragma unroll
    for (int ii = 0; ii < 4; ii++) {
        float hr = g_hn[rowArr][i0 + ty * 4 + ii];
        float4 o;
        o.x = hr + hc[0] - acc[ii][0];
        o.y = hr + hc[1] - acc[ii][1];
        o.z = hr + hc[2] - acc[ii][2];
        o.w = hr + hc[3] - acc[ii][3];
        *(float4*)&Cm[(size_t)(i0 + ty * 4 + ii) * NPTS + j0 + tx * 4] = o;
    }
}

// ---------------------------------------------------------------------------
// Fused softmin: one block = 64-row stripe of one matrix. Computes complete
// row-LSE partials (log2 domain) + per-stripe column partials in one read.
//   m=0 (xy): full width; row dir -> ft partials, col dir -> gt partials.
//   m=1/2 (xx/yy): cols [0,(s+1)*64): rows get triangle+diag directly,
//                  col partials (cols < s*64) supply the upper triangle.
// logits (base 2): u = -12 + pot_col[c]*ieL - C*ieL (row dir),
//                  v = -12 + pot_row[r]*ieL - C*ieL (col dir),  ieL = log2e/eps
// ---------------------------------------------------------------------------
__global__ __launch_bounds__(256) void fused_softmin(int mode, float ieL, int srcbuf) {
    int s = blockIdx.x;
    int m = blockIdx.y;
    int b = blockIdx.z;
    int mat = b * 3 + m;
    const float* C = g_C[mat];
    const float* prow = g_pot[srcbuf][b][(m == 0) ? 0 : (m + 1)];
    const float* pcol = g_pot[srcbuf][b][(m == 0) ? 1 : (m + 1)];
    int colTot  = (m == 0) ? NPTS : (s + 1) * 64;   // row-dir coverage
    int colCols = (m == 0) ? NPTS : s * 64;          // emit col partials below diag

    __shared__ __align__(16) float hbv[256];
    __shared__ float hav[64];
    __shared__ __align__(16) float wm[8][256];
    __shared__ __align__(16) float ws[8][256];
    __shared__ float cm[256], cs[256];

    int tid = threadIdx.x, w = tid >> 5, l = tid & 31;

    if (tid < 64) {
        int r = s * 64 + tid;
        hav[tid] = mode ? fmaf(prow[r], ieL, -12.0f) : -12.0f;  // log2(1/4096) = -12
    }

    float mr[8], sr[8];
    #pragma unroll
    for (int k = 0; k < 8; k++) { mr[k] = -FLTMAX; sr[k] = 0.f; }

    for (int c0 = 0; c0 < colTot; c0 += 256) {
        int valid = min(256, colTot - c0);   // always a multiple of 64
        {
            int c = c0 + tid; if (c > NPTS - 1) c = NPTS - 1;
            hbv[tid] = mode ? fmaf(pcol[c], ieL, -12.0f) : -12.0f;
        }
        cm[tid] = -FLTMAX; cs[tid] = 0.f;
        __syncthreads();

        const float4* hb4 = (const float4*)hbv;
        float4 hbA = hb4[l], hbB = hb4[32 + l];
        bool va = (l * 4 < valid), vb = (128 + l * 4 < valid);

        #pragma unroll
        for (int st = 0; st < 2; st++) {
            int rloc = st * 32 + w * 4;
            int r0 = s * 64 + rloc;
            float4 ua[4], ub[4];
            #pragma unroll
            for (int rr = 0; rr < 4; rr++) {
                const float4* Cr = (const float4*)(C + (size_t)(r0 + rr) * NPTS + c0);
                if (va) {
                    float4 c4 = Cr[l];
                    ua[rr].x = fmaf(-c4.x, ieL, hbA.x);
                    ua[rr].y = fmaf(-c4.y, ieL, hbA.y);
                    ua[rr].z = fmaf(-c4.z, ieL, hbA.z);
                    ua[rr].w = fmaf(-c4.w, ieL, hbA.w);
                } else ua[rr] = make_float4(-FLTMAX, -FLTMAX, -FLTMAX, -FLTMAX);
                if (vb) {
                    float4 c4 = Cr[32 + l];
                    ub[rr].x = fmaf(-c4.x, ieL, hbB.x);
                    ub[rr].y = fmaf(-c4.y, ieL, hbB.y);
                    ub[rr].z = fmaf(-c4.z, ieL, hbB.z);
                    ub[rr].w = fmaf(-c4.w, ieL, hbB.w);
                } else ub[rr] = make_float4(-FLTMAX, -FLTMAX, -FLTMAX, -FLTMAX);
            }
            // ---- row direction: two-pass per chunk via warp reductions ----
            #pragma unroll
            for (int rr = 0; rr < 4; rr++) {
                float mx = fmaxf(fmaxf(fmaxf(ua[rr].x, ua[rr].y), fmaxf(ua[rr].z, ua[rr].w)),
                                 fmaxf(fmaxf(ub[rr].x, ub[rr].y), fmaxf(ub[rr].z, ub[rr].w)));
                #pragma unroll
                for (int o = 16; o > 0; o >>= 1) mx = fmaxf(mx, __shfl_xor_sync(0xffffffffu, mx, o));
                float sm = ex2f(ua[rr].x - mx) + ex2f(ua[rr].y - mx) +
                           ex2f(ua[rr].z - mx) + ex2f(ua[rr].w - mx) +
                           ex2f(ub[rr].x - mx) + ex2f(ub[rr].y - mx) +
                           ex2f(ub[rr].z - mx) + ex2f(ub[rr].w - mx);
                #pragma unroll
                for (int o = 16; o > 0; o >>= 1) sm += __shfl_xor_sync(0xffffffffu, sm, o);
                int k = st * 4 + rr;
                float mn = fmaxf(mr[k], mx);
                sr[k] = sr[k] * ex2f(mr[k] - mn) + sm * ex2f(mx - mn);
                mr[k] = mn;
            }
            // ---- column direction: per-warp 4-row partials -> smem merge ----
            float d0 = hav[rloc + 0], d1 = hav[rloc + 1], d2 = hav[rloc + 2], d3 = hav[rloc + 3];
            float4 vmA, vsA, vmB, vsB;
            #define COLOP(RM, RS, U0, U1, U2, U3, HB) {                         \
                float w0 = (U0) + d0, w1 = (U1) + d1, w2 = (U2) + d2, w3 = (U3) + d3; \
                float mx_ = fmaxf(fmaxf(w0, w1), fmaxf(w2, w3));                \
                RS = ex2f(w0 - mx_) + ex2f(w1 - mx_) + ex2f(w2 - mx_) + ex2f(w3 - mx_); \
                RM = mx_ - (HB); }
            COLOP(vmA.x, vsA.x, ua[0].x, ua[1].x, ua[2].x, ua[3].x, hbA.x);
            COLOP(vmA.y, vsA.y, ua[0].y, ua[1].y, ua[2].y, ua[3].y, hbA.y);
            COLOP(vmA.z, vsA.z, ua[0].z, ua[1].z, ua[2].z, ua[3].z, hbA.z);
            COLOP(vmA.w, vsA.w, ua[0].w, ua[1].w, ua[2].w, ua[3].w, hbA.w);
            COLOP(vmB.x, vsB.x, ub[0].x, ub[1].x, ub[2].x, ub[3].x, hbB.x);
            COLOP(vmB.y, vsB.y, ub[0].y, ub[1].y, ub[2].y, ub[3].y, hbB.y);
            COLOP(vmB.z, vsB.z, ub[0].z, ub[1].z, ub[2].z, ub[3].z, hbB.z);
            COLOP(vmB.w, vsB.w, ub[0].w, ub[1].w, ub[2].w, ub[3].w, hbB.w);
            #undef COLOP
            *(float4*)&wm[w][l * 4] = vmA;
            *(float4*)&wm[w][128 + l * 4] = vmB;
            *(float4*)&ws[w][l * 4] = vsA;
            *(float4*)&ws[w][128 + l * 4] = vsB;
            __syncthreads();
            {   // merge 8 warp partials for column tid into running stripe state
                float bm = wm[0][tid];
                #pragma unroll
                for (int q = 1; q < 8; q++) bm = fmaxf(bm, wm[q][tid]);
                float bs = 0.f;
                #pragma unroll
                for (int q = 0; q < 8; q++) bs += ws[q][tid] * ex2f(wm[q][tid] - bm);
                float mo = cm[tid];
                float mn = fmaxf(mo, bm);
                cs[tid] = cs[tid] * ex2f(mo - mn) + bs * ex2f(bm - mn);
                cm[tid] = mn;
            }
            __syncthreads();
        }
        if (c0 + tid < colCols) {
            g_cpm[mat][s][c0 + tid] = cm[tid];
            g_cps[mat][s][c0 + tid] = cs[tid];
        }
    }
    if (l == 0) {
        #pragma unroll
        for (int k = 0; k < 8; k++) {
            int row = s * 64 + (k >> 2) * 32 + w * 4 + (k & 3);
            g_rpm[mat][row] = mr[k];
            g_rps[mat][row] = sr[k];
        }
    }
}

// ---------------------------------------------------------------------------
// Combiner: merge partials -> potentials. grid (16, 4 types, B), 256 thr.
//   t=0 ft:  rowpart(xy) complete.       t=1 gt: 64 colparts(xy).
//   t=2 fa:  rowpart(xx) + colparts(xx) from stripes > stripe(i).  t=3: yy.
// res = -eps*ln2*(M + log2 S); mode==1 blends 0.5 with previous potential.
// ---------------------------------------------------------------------------
__global__ __launch_bounds__(256) void combiner(int mode, float neg_eps_ln2, int srcbuf) {
    int i = blockIdx.x * 256 + threadIdx.x;
    int t = blockIdx.y;
    int b = blockIdx.z;
    float M, S;
    if (t == 0) {
        int mat = b * 3;
        M = g_rpm[mat][i]; S = g_rps[mat][i];
    } else if (t == 1) {
        int mat = b * 3;
        M = g_cpm[mat][0][i]; S = g_cps[mat][0][i];
        for (int st = 1; st < 64; st++) {
            float m2 = g_cpm[mat][st][i], s2 = g_cps[mat][st][i];
            float mn = fmaxf(M, m2);
            S = S * ex2f(M - mn) + s2 * ex2f(m2 - mn);
            M = mn;
        }
    } else {
        int mat = b * 3 + (t - 1);
        M = g_rpm[mat][i]; S = g_rps[mat][i];
        for (int st = (i >> 6) + 1; st < 64; st++) {
            float m2 = g_cpm[mat][st][i], s2 = g_cps[mat][st][i];
            float mn = fmaxf(M, m2);
            S = S * ex2f(M - mn) + s2 * ex2f(m2 - mn);
            M = mn;
        }
    }
    float res = neg_eps_ln2 * (M + lg2f(S));
    if (mode == 1) res = 0.5f * (g_pot[srcbuf][b][t][i] + res);
    g_pot[srcbuf ^ 1][b][t][i] = res;
}

// ---------------------------------------------------------------------------
// Final reduction: loss = (1/(B*N)) * sum (f_ba - f_aa + g_ab - g_bb)
// ---------------------------------------------------------------------------
__global__ __launch_bounds__(256) void reduce_kernel(float* __restrict__ out, int buf) {
    __shared__ float sred[8];
    int tid = threadIdx.x;
    float s = 0.f;
    for (int k = tid; k < BATCH * NPTS; k += 256) {
        int b = k >> 12, i = k & (NPTS - 1);
        const float* pb = &g_pot[buf][b][0][0];
        s += (pb[0 * NPTS + i] - pb[2 * NPTS + i]) +
             (pb[1 * NPTS + i] - pb[3 * NPTS + i]);
    }
    #pragma unroll
    for (int o = 16; o; o >>= 1) s += __shfl_xor_sync(0xffffffffu, s, o);
    if ((tid & 31) == 0) sred[tid >> 5] = s;
    __syncthreads();
    if (tid == 0) {
        float tot = sred[0];
        #pragma unroll
        for (int w = 1; w < 8; w++) tot += sred[w];
        out[0] = tot * (1.0f / (float)(BATCH * NPTS));
    }
}

extern "C" void kernel_launch(void* const* d_in, const int* in_sizes, int n_in,
                              void* d_out, int out_size) {
    const float* x = (const float*)d_in[0];
    const float* y = (const float*)d_in[1];
    float* out = (float*)d_out;

    // epsilon schedule: exp(arange(2 ln 16, 2 ln 0.05, 2 ln 0.9)) ++ [0.05^2]
    float eps_list[56];
    {
        double start = 2.0 * log(16.0);
        double step = 2.0 * log(0.9);
        for (int k = 0; k < 55; k++)
            eps_list[k] = (float)exp(start + (double)k * step);
        eps_list[55] = (float)(0.05 * 0.05);
    }
    const double LOG2E = 1.4426950408889634;
    const double LN2 = 0.6931471805599453;

    norm_kernel<<<(8 * NPTS) / 256, 256>>>(x, y);
    cost_kernel<<<dim3(64, 64, 12), 256>>>(x, y);

    dim3 fg(64, 3, BATCH);
    dim3 cg(NPTS / 256, 4, BATCH);
    int buf = 0;

    // init at eps0 (no potentials)
    fused_softmin<<<fg, 256>>>(0, (float)(LOG2E / eps_list[0]), buf);
    combiner<<<cg, 256>>>(0, (float)(-(double)eps_list[0] * LN2), buf);
    buf ^= 1;

    // 56 scan steps with 0.5 blending
    for (int k = 0; k < 56; k++) {
        fused_softmin<<<fg, 256>>>(1, (float)(LOG2E / eps_list[k]), buf);
        combiner<<<cg, 256>>>(1, (float)(-(double)eps_list[k] * LN2), buf);
        buf ^= 1;
    }

    // final extrapolation at blur^p, no blending
    fused_softmin<<<fg, 256>>>(1, (float)(LOG2E / eps_list[55]), buf);
    combiner<<<cg, 256>>>(2, (float)(-(double)eps_list[55] * LN2), buf);
    buf ^= 1;

    reduce_kernel<<<1, 256>>>(out, buf);
}